// round 15
// baseline (speedup 1.0000x reference)
#include <cuda_runtime.h>

#define NUM_TREES 256
#define DEPTH 6
#define INPUT_DIM 256
#define BATCH 2048
#define NCOLS (NUM_TREES * DEPTH)   // 1536
#define MAXNZ 256
#define OUTW (NUM_TREES * 2)        // 512
#define TPAD 66                      // padded batch-tile row stride (floats)

// smem layout offsets (bytes)
#define OFF_PACK 67584                        // 256*66*4
#define OFF_COEF (OFF_PACK + 12288)           // 79872  (192 cols * 8 * 8B)
#define OFF_NNZ  (OFF_COEF + 16384)           // 96256
#define OFF_TH   (OFF_NNZ + 768)              // 97024
#define ODT_SMEM (OFF_TH + 1536)              // 98560

// Device scratch
__device__ float2 g_pack[NCOLS * MAXNZ];      // {prescaled idx*TPAD bits, weight}
__device__ int    g_nnz [NCOLS];              // >= 8, multiple of 4
__device__ float  g_coef[NUM_TREES * 64 * 2]; // multilinear coeffs [n][c][tdim]

// packed fp32x2 ops (Blackwell)
__device__ __forceinline__ float2 fma2(float2 a, float2 b, float2 c) {
    unsigned long long A, B, C, R;
    A = *reinterpret_cast<unsigned long long*>(&a);
    B = *reinterpret_cast<unsigned long long*>(&b);
    C = *reinterpret_cast<unsigned long long*>(&c);
    asm("fma.rn.f32x2 %0, %1, %2, %3;" : "=l"(R) : "l"(A), "l"(B), "l"(C));
    return *reinterpret_cast<float2*>(&R);
}
__device__ __forceinline__ float2 add2(float2 a, float2 b) {
    unsigned long long A, B, R;
    A = *reinterpret_cast<unsigned long long*>(&a);
    B = *reinterpret_cast<unsigned long long*>(&b);
    asm("add.rn.f32x2 %0, %1, %2;" : "=l"(R) : "l"(A), "l"(B));
    return *reinterpret_cast<float2*>(&R);
}

// ---------------------------------------------------------------------------
// Prep kernel: blocks 0..191  = sparsemax (8 columns each, Michelot) + compact
//              blocks 192..255 = response -> multilinear coefficient transform
// ---------------------------------------------------------------------------
__global__ void __launch_bounds__(256) prep_kernel(
    const float* __restrict__ fsl, const float* __restrict__ resp)
{
    cudaTriggerProgrammaticLaunchCompletion();

    const int tid  = threadIdx.x;
    const int warp = tid >> 5;
    const int lane = tid & 31;

    if (blockIdx.x < 192) {
        // ---- sparsemax over 8 columns ----
        __shared__ float s[INPUT_DIM * 9];   // [row][col] pad 9
        const int colBase = blockIdx.x * 8;
        #pragma unroll
        for (int k = 0; k < 8; k++) {
            int linear = k * 256 + tid;
            int r = linear >> 3, c = linear & 7;
            s[r * 9 + c] = fsl[r * NCOLS + colBase + c];
        }
        __syncthreads();

        const int col = colBase + warp;
        float v[8];
        #pragma unroll
        for (int j = 0; j < 8; j++) v[j] = s[(j * 32 + lane) * 9 + warp];

        float ss = v[0];
        #pragma unroll
        for (int j = 1; j < 8; j++) ss += v[j];
        #pragma unroll
        for (int o = 16; o > 0; o >>= 1) ss += __shfl_xor_sync(~0u, ss, o);
        float tau = (ss - 1.0f) / 256.0f;

        int cprev = 256;
        for (int it = 0; it < 64; it++) {
            float ps = 0.0f; int pc = 0;
            #pragma unroll
            for (int j = 0; j < 8; j++)
                if (v[j] > tau) { ps += v[j]; pc++; }
            #pragma unroll
            for (int o = 16; o > 0; o >>= 1) {
                ps += __shfl_xor_sync(~0u, ps, o);
                pc += __shfl_xor_sync(~0u, pc, o);
            }
            tau = (ps - 1.0f) / (float)pc;
            if (pc == cprev) break;
            cprev = pc;
        }

        // compaction with prescaled offsets (idx * TPAD)
        const unsigned ltmask = (1u << lane) - 1u;
        int total = 0;
        #pragma unroll
        for (int j = 0; j < 8; j++) {
            float w = v[j] - tau;
            bool nz = (w > 0.0f);
            unsigned m = __ballot_sync(~0u, nz);
            if (nz) {
                int pos = total + __popc(m & ltmask);
                g_pack[col * MAXNZ + pos] =
                    make_float2(__int_as_float((j * 32 + lane) * TPAD), w);
            }
            total += __popc(m);
        }
        // pad to 8 minimum, else to multiple of 4
        int tot = (total <= 8) ? 8 : ((total + 3) & ~3);
        if (lane < tot - total)
            g_pack[col * MAXNZ + total + lane] = make_float2(__int_as_float(0), 0.0f);
        if (lane == 0) g_nnz[col] = tot;
    } else {
        // ---- coefficient transform: warp = (tree, tdim) ----
        const int cb = blockIdx.x - 192;
        const int n  = cb * 4 + (warp >> 1);
        const int t  = warp & 1;
        float r0 = resp[(n * 2 + t) * 64 + lane];
        float r1 = resp[(n * 2 + t) * 64 + 32 + lane];
        #pragma unroll
        for (int d = 0; d < 5; d++) {
            int m = 1 << d;
            float o0 = __shfl_xor_sync(~0u, r0, m);
            float o1 = __shfl_xor_sync(~0u, r1, m);
            bool hi = (lane >> d) & 1;
            r0 = hi ? (o0 - r0) : o0;
            r1 = hi ? (o1 - r1) : o1;
        }
        { float tmp = r0; r0 = r1; r1 = tmp - r1; }
        g_coef[(n * 64 + lane)      * 2 + t] = r0;
        g_coef[(n * 64 + 32 + lane) * 2 + t] = r1;
    }
}

// ---------------------------------------------------------------------------
// Main kernel: block = (tree group of 32, batch tile of 64 rows), 512 threads.
// Branch-free gather fast path; overflow patched once per tree via bitmask.
// ---------------------------------------------------------------------------
__global__ void __launch_bounds__(512, 2) odt_main(
    const float* __restrict__ inputs,
    const float* __restrict__ thr,
    const float* __restrict__ logT,
    float* __restrict__ out)
{
    extern __shared__ __align__(16) char smem[];
    float*  s_in    = (float*) smem;                 // [256][66]
    float4* s_pack4 = (float4*)(smem + OFF_PACK);    // [192][4] f4 (=8 f2)
    float4* s_coef4 = (float4*)(smem + OFF_COEF);    // [32][32] f4
    int*    s_nnz   = (int*)   (smem + OFF_NNZ);     // [192]
    float2* s_th    = (float2*)(smem + OFF_TH);      // [192] {bias, scale}

    const int tid  = threadIdx.x;
    const int lane = tid & 31;
    const int sub  = tid >> 5;
    const int grp  = blockIdx.x;          // 0..7
    const int tileB = blockIdx.y * 64;
    const int nBase = grp * 32;
    const int colBase = nBase * DEPTH;    // grp*192

    // ---- prep-independent staging (vectorized LDG.128) ----
    // thread handles feature quad i4 = (tid&63)*4, rows b = tid>>6 + 8*e
    {
        const int i4 = (tid & 63) * 4;
        const int bb = tid >> 6;          // 0..7
        #pragma unroll
        for (int e = 0; e < 8; e++) {
            int b = bb + e * 8;
            float4 v = *(const float4*)(inputs + (size_t)(tileB + b) * INPUT_DIM + i4);
            s_in[(i4 + 0) * TPAD + b] = v.x;
            s_in[(i4 + 1) * TPAD + b] = v.y;
            s_in[(i4 + 2) * TPAD + b] = v.z;
            s_in[(i4 + 3) * TPAD + b] = v.w;
        }
    }
    // folded threshold transform: t = acc*scale + bias
    if (tid < 192) {
        int gcol = colBase + tid;
        float sc = 0.5f * expf(-logT[gcol]);
        s_th[tid] = make_float2(0.5f - thr[gcol] * sc, sc);
    }

    // ---- wait for prep results, then stage them ----
    cudaGridDependencySynchronize();

    const float4* gp4 = (const float4*)g_pack;
    {
        int idx = tid;
        int cl = idx >> 2, j = idx & 3;
        s_pack4[idx] = gp4[(colBase + cl) * (MAXNZ / 2) + j];
        idx = 512 + tid;
        if (idx < 768) {
            cl = idx >> 2; j = idx & 3;
            s_pack4[idx] = gp4[(colBase + cl) * (MAXNZ / 2) + j];
        }
    }
    const float4* gc4 = (const float4*)g_coef;
    s_coef4[tid]       = gc4[nBase * 32 + tid];
    s_coef4[512 + tid] = gc4[nBase * 32 + 512 + tid];
    if (tid < 192) s_nnz[tid] = g_nnz[colBase + tid];
    __syncthreads();

    // warp-uniform overflow bitmask for this warp's 12 columns
    unsigned over = 0;
    #pragma unroll
    for (int q = 0; q < 12; q++)
        if (s_nnz[sub * 12 + q] > 8) over |= 1u << q;

    const int base2 = 2 * lane;
    float2 res[2][2];   // [k][row]

    #pragma unroll
    for (int k = 0; k < 2; k++) {
        const int nL = sub * 2 + k;

        // ---- branch-free gather fast path: acc for all 6 depths ----
        float2 acc[DEPTH];
        #pragma unroll
        for (int d = 0; d < DEPTH; d++) {
            const int colL = nL * DEPTH + d;
            const float4* pk = s_pack4 + colL * 4;
            float4 a = pk[0], b = pk[1], c = pk[2], e = pk[3];

            float2 x0 = *(const float2*)(s_in + __float_as_int(a.x) + base2);
            float2 x1 = *(const float2*)(s_in + __float_as_int(a.z) + base2);
            float2 x2 = *(const float2*)(s_in + __float_as_int(b.x) + base2);
            float2 x3 = *(const float2*)(s_in + __float_as_int(b.z) + base2);
            float2 x4 = *(const float2*)(s_in + __float_as_int(c.x) + base2);
            float2 x5 = *(const float2*)(s_in + __float_as_int(c.z) + base2);
            float2 x6 = *(const float2*)(s_in + __float_as_int(e.x) + base2);
            float2 x7 = *(const float2*)(s_in + __float_as_int(e.z) + base2);

            float2 a0 = make_float2(0.0f, 0.0f);
            float2 a1 = make_float2(0.0f, 0.0f);
            a0 = fma2(x0, make_float2(a.y, a.y), a0);
            a1 = fma2(x1, make_float2(a.w, a.w), a1);
            a0 = fma2(x2, make_float2(b.y, b.y), a0);
            a1 = fma2(x3, make_float2(b.w, b.w), a1);
            a0 = fma2(x4, make_float2(c.y, c.y), a0);
            a1 = fma2(x5, make_float2(c.w, c.w), a1);
            a0 = fma2(x6, make_float2(e.y, e.y), a0);
            a1 = fma2(x7, make_float2(e.w, e.w), a1);
            acc[d] = add2(a0, a1);
        }

        // ---- single rare patch branch for overflow columns ----
        if (over & (0x3fu << (k * 6))) {
            #pragma unroll
            for (int d = 0; d < DEPTH; d++) {
                if (over & (1u << (k * 6 + d))) {
                    const int colL = nL * DEPTH + d;
                    const int nn = s_nnz[colL];
                    const float2* gq = g_pack + (size_t)(colBase + colL) * MAXNZ;
                    for (int j = 8; j < nn; j++) {
                        float2 q = __ldg(gq + j);
                        float2 x = *(const float2*)(s_in + __float_as_int(q.x) + base2);
                        acc[d] = fma2(x, make_float2(q.y, q.y), acc[d]);
                    }
                }
            }
        }

        // ---- clip to p (packed threshold fma, scalar clips) ----
        float2 pp0[DEPTH], pp1[DEPTH];
        #pragma unroll
        for (int d = 0; d < DEPTH; d++) {
            float2 th = s_th[nL * DEPTH + d];
            float2 t = fma2(acc[d], make_float2(th.y, th.y),
                            make_float2(th.x, th.x));
            float pA = fminf(fmaxf(t.x, 0.0f), 1.0f);
            float pB = fminf(fmaxf(t.y, 0.0f), 1.0f);
            pp0[d] = make_float2(pA, pA);
            pp1[d] = make_float2(pB, pB);
        }

        // ---- multilinear evaluation, tdims packed ----
        const float4* cf = s_coef4 + nL * 32;
        float2 w0[8], w1[8];
        #pragma unroll
        for (int j = 0; j < 8; j++) {
            float2 v0a, v0b, v1a, v1b;
            {
                float4 c0 = cf[4 * j + 0], c1 = cf[4 * j + 1];
                float2 lo0 = make_float2(c0.x, c0.y), hi0 = make_float2(c0.z, c0.w);
                float2 lo1 = make_float2(c1.x, c1.y), hi1 = make_float2(c1.z, c1.w);
                float2 u0r0 = fma2(pp0[0], hi0, lo0);
                float2 u0r1 = fma2(pp1[0], hi0, lo0);
                float2 u1r0 = fma2(pp0[0], hi1, lo1);
                float2 u1r1 = fma2(pp1[0], hi1, lo1);
                v0a = fma2(pp0[1], u1r0, u0r0);
                v1a = fma2(pp1[1], u1r1, u0r1);
            }
            {
                float4 c2 = cf[4 * j + 2], c3 = cf[4 * j + 3];
                float2 lo2 = make_float2(c2.x, c2.y), hi2 = make_float2(c2.z, c2.w);
                float2 lo3 = make_float2(c3.x, c3.y), hi3 = make_float2(c3.z, c3.w);
                float2 u2r0 = fma2(pp0[0], hi2, lo2);
                float2 u2r1 = fma2(pp1[0], hi2, lo2);
                float2 u3r0 = fma2(pp0[0], hi3, lo3);
                float2 u3r1 = fma2(pp1[0], hi3, lo3);
                v0b = fma2(pp0[1], u3r0, u2r0);
                v1b = fma2(pp1[1], u3r1, u2r1);
            }
            w0[j] = fma2(pp0[2], v0b, v0a);
            w1[j] = fma2(pp1[2], v1b, v1a);
        }
        float2 x0[4], x1[4];
        #pragma unroll
        for (int j = 0; j < 4; j++) {
            x0[j] = fma2(pp0[3], w0[2 * j + 1], w0[2 * j]);
            x1[j] = fma2(pp1[3], w1[2 * j + 1], w1[2 * j]);
        }
        float2 y00 = fma2(pp0[4], x0[1], x0[0]);
        float2 y01 = fma2(pp0[4], x0[3], x0[2]);
        float2 y10 = fma2(pp1[4], x1[1], x1[0]);
        float2 y11 = fma2(pp1[4], x1[3], x1[2]);
        res[k][0] = fma2(pp0[5], y01, y00);
        res[k][1] = fma2(pp1[5], y11, y10);
    }

    // store: 4 consecutive trees' (t0,t1) per row -> STG.128
    const int b0 = tileB + 2 * lane;
    float* o0 = out + (size_t)b0 * OUTW + grp * 64 + sub * 4;
    float* o1 = o0 + OUTW;
    *(float4*)o0 = make_float4(res[0][0].x, res[0][0].y, res[1][0].x, res[1][0].y);
    *(float4*)o1 = make_float4(res[0][1].x, res[0][1].y, res[1][1].x, res[1][1].y);
}

// ---------------------------------------------------------------------------
extern "C" void kernel_launch(void* const* d_in, const int* in_sizes, int n_in,
                              void* d_out, int out_size) {
    const float* inputs = (const float*)d_in[0];
    const float* fsl    = (const float*)d_in[1];
    const float* thr    = (const float*)d_in[2];
    const float* logT   = (const float*)d_in[3];
    const float* resp   = (const float*)d_in[4];
    float* out = (float*)d_out;

    cudaFuncSetAttribute(odt_main, cudaFuncAttributeMaxDynamicSharedMemorySize,
                         ODT_SMEM);

    prep_kernel<<<256, 256>>>(fsl, resp);

    cudaLaunchConfig_t cfg = {};
    cfg.gridDim = dim3(8, 32);
    cfg.blockDim = dim3(512);
    cfg.dynamicSmemBytes = ODT_SMEM;
    cudaLaunchAttribute attrs[1];
    attrs[0].id = cudaLaunchAttributeProgrammaticStreamSerialization;
    attrs[0].val.programmaticStreamSerializationAllowed = 1;
    cfg.attrs = attrs;
    cfg.numAttrs = 1;
    cudaLaunchKernelEx(&cfg, odt_main, inputs, thr, logT, out);
}

// round 16
// speedup vs baseline: 1.2117x; 1.2117x over previous
#include <cuda_runtime.h>

#define NUM_TREES 256
#define DEPTH 6
#define INPUT_DIM 256
#define BATCH 2048
#define NCOLS (NUM_TREES * DEPTH)   // 1536
#define MAXNZ 256
#define OUTW (NUM_TREES * 2)        // 512
#define TPAD 66                      // padded batch-tile row stride (floats)

// smem layout offsets (bytes)
#define OFF_PACK 67584                        // 256*66*4
#define OFF_COEF (OFF_PACK + 12288)           // 79872  (192 cols * 8 * 8B)
#define OFF_NNZ  (OFF_COEF + 16384)           // 96256
#define OFF_TH   (OFF_NNZ + 768)              // 97024
#define ODT_SMEM (OFF_TH + 1536)              // 98560

// Device scratch
__device__ float2 g_pack[NCOLS * MAXNZ];      // {prescaled idx*TPAD bits, weight}
__device__ int    g_nnz [NCOLS];              // >= 8, multiple of 4
__device__ float  g_coef[NUM_TREES * 64 * 2]; // multilinear coeffs [n][c][tdim]

// packed fp32x2 ops (Blackwell)
__device__ __forceinline__ float2 fma2(float2 a, float2 b, float2 c) {
    unsigned long long A, B, C, R;
    A = *reinterpret_cast<unsigned long long*>(&a);
    B = *reinterpret_cast<unsigned long long*>(&b);
    C = *reinterpret_cast<unsigned long long*>(&c);
    asm("fma.rn.f32x2 %0, %1, %2, %3;" : "=l"(R) : "l"(A), "l"(B), "l"(C));
    return *reinterpret_cast<float2*>(&R);
}
__device__ __forceinline__ float2 add2(float2 a, float2 b) {
    unsigned long long A, B, R;
    A = *reinterpret_cast<unsigned long long*>(&a);
    B = *reinterpret_cast<unsigned long long*>(&b);
    asm("add.rn.f32x2 %0, %1, %2;" : "=l"(R) : "l"(A), "l"(B));
    return *reinterpret_cast<float2*>(&R);
}

// ---------------------------------------------------------------------------
// Prep kernel: blocks 0..191  = sparsemax (8 columns each, Michelot) + compact
//              blocks 192..255 = response -> multilinear coefficient transform
// ---------------------------------------------------------------------------
__global__ void __launch_bounds__(256) prep_kernel(
    const float* __restrict__ fsl, const float* __restrict__ resp)
{
    cudaTriggerProgrammaticLaunchCompletion();

    const int tid  = threadIdx.x;
    const int warp = tid >> 5;
    const int lane = tid & 31;

    if (blockIdx.x < 192) {
        // ---- sparsemax over 8 columns ----
        __shared__ float s[INPUT_DIM * 9];   // [row][col] pad 9
        const int colBase = blockIdx.x * 8;
        #pragma unroll
        for (int k = 0; k < 8; k++) {
            int linear = k * 256 + tid;
            int r = linear >> 3, c = linear & 7;
            s[r * 9 + c] = fsl[r * NCOLS + colBase + c];
        }
        __syncthreads();

        const int col = colBase + warp;
        float v[8];
        #pragma unroll
        for (int j = 0; j < 8; j++) v[j] = s[(j * 32 + lane) * 9 + warp];

        float ss = v[0];
        #pragma unroll
        for (int j = 1; j < 8; j++) ss += v[j];
        #pragma unroll
        for (int o = 16; o > 0; o >>= 1) ss += __shfl_xor_sync(~0u, ss, o);
        float tau = (ss - 1.0f) / 256.0f;

        int cprev = 256;
        for (int it = 0; it < 64; it++) {
            float ps = 0.0f; int pc = 0;
            #pragma unroll
            for (int j = 0; j < 8; j++)
                if (v[j] > tau) { ps += v[j]; pc++; }
            #pragma unroll
            for (int o = 16; o > 0; o >>= 1) {
                ps += __shfl_xor_sync(~0u, ps, o);
                pc += __shfl_xor_sync(~0u, pc, o);
            }
            tau = (ps - 1.0f) / (float)pc;
            if (pc == cprev) break;
            cprev = pc;
        }

        // compaction with prescaled offsets (idx * TPAD)
        const unsigned ltmask = (1u << lane) - 1u;
        int total = 0;
        #pragma unroll
        for (int j = 0; j < 8; j++) {
            float w = v[j] - tau;
            bool nz = (w > 0.0f);
            unsigned m = __ballot_sync(~0u, nz);
            if (nz) {
                int pos = total + __popc(m & ltmask);
                g_pack[col * MAXNZ + pos] =
                    make_float2(__int_as_float((j * 32 + lane) * TPAD), w);
            }
            total += __popc(m);
        }
        // pad to 8 minimum, else to multiple of 4
        int tot = (total <= 8) ? 8 : ((total + 3) & ~3);
        if (lane < tot - total)
            g_pack[col * MAXNZ + total + lane] = make_float2(__int_as_float(0), 0.0f);
        if (lane == 0) g_nnz[col] = tot;
    } else {
        // ---- coefficient transform: warp = (tree, tdim) ----
        const int cb = blockIdx.x - 192;
        const int n  = cb * 4 + (warp >> 1);
        const int t  = warp & 1;
        float r0 = resp[(n * 2 + t) * 64 + lane];
        float r1 = resp[(n * 2 + t) * 64 + 32 + lane];
        #pragma unroll
        for (int d = 0; d < 5; d++) {
            int m = 1 << d;
            float o0 = __shfl_xor_sync(~0u, r0, m);
            float o1 = __shfl_xor_sync(~0u, r1, m);
            bool hi = (lane >> d) & 1;
            r0 = hi ? (o0 - r0) : o0;
            r1 = hi ? (o1 - r1) : o1;
        }
        { float tmp = r0; r0 = r1; r1 = tmp - r1; }
        g_coef[(n * 64 + lane)      * 2 + t] = r0;
        g_coef[(n * 64 + 32 + lane) * 2 + t] = r1;
    }
}

// ---------------------------------------------------------------------------
// Main kernel: block = (tree group of 32, batch tile of 64 rows), 512 threads.
// Branch-free gather fast path; overflow patched once per tree via bitmask.
// ---------------------------------------------------------------------------
__global__ void __launch_bounds__(512, 2) odt_main(
    const float* __restrict__ inputs,
    const float* __restrict__ thr,
    const float* __restrict__ logT,
    float* __restrict__ out)
{
    extern __shared__ __align__(16) char smem[];
    float*  s_in    = (float*) smem;                 // [256][66]
    float4* s_pack4 = (float4*)(smem + OFF_PACK);    // [192][4] f4 (=8 f2)
    float4* s_coef4 = (float4*)(smem + OFF_COEF);    // [32][32] f4
    int*    s_nnz   = (int*)   (smem + OFF_NNZ);     // [192]
    float2* s_th    = (float2*)(smem + OFF_TH);      // [192] {bias, scale}

    const int tid  = threadIdx.x;
    const int lane = tid & 31;
    const int sub  = tid >> 5;
    const int grp  = blockIdx.x;          // 0..7
    const int tileB = blockIdx.y * 64;
    const int nBase = grp * 32;
    const int colBase = nBase * DEPTH;    // grp*192

    // ---- prep-independent staging ----
    #pragma unroll
    for (int e = 0; e < 32; e++) {
        int linear = e * 512 + tid;
        int i = linear & 255, b = linear >> 8;
        s_in[i * TPAD + b] = inputs[(tileB + b) * INPUT_DIM + i];
    }
    // folded threshold transform: t = acc*scale + bias
    if (tid < 192) {
        int gcol = colBase + tid;
        float sc = 0.5f * expf(-logT[gcol]);
        s_th[tid] = make_float2(0.5f - thr[gcol] * sc, sc);
    }

    // ---- wait for prep results, then stage them ----
    cudaGridDependencySynchronize();

    const float4* gp4 = (const float4*)g_pack;
    {
        int idx = tid;
        int cl = idx >> 2, j = idx & 3;
        s_pack4[idx] = gp4[(colBase + cl) * (MAXNZ / 2) + j];
        idx = 512 + tid;
        if (idx < 768) {
            cl = idx >> 2; j = idx & 3;
            s_pack4[idx] = gp4[(colBase + cl) * (MAXNZ / 2) + j];
        }
    }
    const float4* gc4 = (const float4*)g_coef;
    s_coef4[tid]       = gc4[nBase * 32 + tid];
    s_coef4[512 + tid] = gc4[nBase * 32 + 512 + tid];
    if (tid < 192) s_nnz[tid] = g_nnz[colBase + tid];
    __syncthreads();

    // warp-uniform overflow bitmask for this warp's 12 columns
    unsigned over = 0;
    #pragma unroll
    for (int q = 0; q < 12; q++)
        if (s_nnz[sub * 12 + q] > 8) over |= 1u << q;

    const int base2 = 2 * lane;
    float2 res[2][2];   // [k][row]

    #pragma unroll
    for (int k = 0; k < 2; k++) {
        const int nL = sub * 2 + k;

        // ---- branch-free gather fast path: acc for all 6 depths ----
        float2 acc[DEPTH];
        #pragma unroll
        for (int d = 0; d < DEPTH; d++) {
            const int colL = nL * DEPTH + d;
            const float4* pk = s_pack4 + colL * 4;
            float4 a = pk[0], b = pk[1], c = pk[2], e = pk[3];

            float2 x0 = *(const float2*)(s_in + __float_as_int(a.x) + base2);
            float2 x1 = *(const float2*)(s_in + __float_as_int(a.z) + base2);
            float2 x2 = *(const float2*)(s_in + __float_as_int(b.x) + base2);
            float2 x3 = *(const float2*)(s_in + __float_as_int(b.z) + base2);
            float2 x4 = *(const float2*)(s_in + __float_as_int(c.x) + base2);
            float2 x5 = *(const float2*)(s_in + __float_as_int(c.z) + base2);
            float2 x6 = *(const float2*)(s_in + __float_as_int(e.x) + base2);
            float2 x7 = *(const float2*)(s_in + __float_as_int(e.z) + base2);

            float2 a0 = make_float2(0.0f, 0.0f);
            float2 a1 = make_float2(0.0f, 0.0f);
            a0 = fma2(x0, make_float2(a.y, a.y), a0);
            a1 = fma2(x1, make_float2(a.w, a.w), a1);
            a0 = fma2(x2, make_float2(b.y, b.y), a0);
            a1 = fma2(x3, make_float2(b.w, b.w), a1);
            a0 = fma2(x4, make_float2(c.y, c.y), a0);
            a1 = fma2(x5, make_float2(c.w, c.w), a1);
            a0 = fma2(x6, make_float2(e.y, e.y), a0);
            a1 = fma2(x7, make_float2(e.w, e.w), a1);
            acc[d] = add2(a0, a1);
        }

        // ---- single rare patch branch for overflow columns ----
        if (over & (0x3fu << (k * 6))) {
            #pragma unroll
            for (int d = 0; d < DEPTH; d++) {
                if (over & (1u << (k * 6 + d))) {
                    const int colL = nL * DEPTH + d;
                    const int nn = s_nnz[colL];
                    const float2* gq = g_pack + (size_t)(colBase + colL) * MAXNZ;
                    for (int j = 8; j < nn; j++) {
                        float2 q = __ldg(gq + j);
                        float2 x = *(const float2*)(s_in + __float_as_int(q.x) + base2);
                        acc[d] = fma2(x, make_float2(q.y, q.y), acc[d]);
                    }
                }
            }
        }

        // ---- clip to p (packed threshold fma, scalar clips) ----
        float2 pp0[DEPTH], pp1[DEPTH];
        #pragma unroll
        for (int d = 0; d < DEPTH; d++) {
            float2 th = s_th[nL * DEPTH + d];
            float2 t = fma2(acc[d], make_float2(th.y, th.y),
                            make_float2(th.x, th.x));
            float pA = fminf(fmaxf(t.x, 0.0f), 1.0f);
            float pB = fminf(fmaxf(t.y, 0.0f), 1.0f);
            pp0[d] = make_float2(pA, pA);
            pp1[d] = make_float2(pB, pB);
        }

        // ---- multilinear evaluation, tdims packed ----
        const float4* cf = s_coef4 + nL * 32;
        float2 w0[8], w1[8];
        #pragma unroll
        for (int j = 0; j < 8; j++) {
            float2 v0a, v0b, v1a, v1b;
            {
                float4 c0 = cf[4 * j + 0], c1 = cf[4 * j + 1];
                float2 lo0 = make_float2(c0.x, c0.y), hi0 = make_float2(c0.z, c0.w);
                float2 lo1 = make_float2(c1.x, c1.y), hi1 = make_float2(c1.z, c1.w);
                float2 u0r0 = fma2(pp0[0], hi0, lo0);
                float2 u0r1 = fma2(pp1[0], hi0, lo0);
                float2 u1r0 = fma2(pp0[0], hi1, lo1);
                float2 u1r1 = fma2(pp1[0], hi1, lo1);
                v0a = fma2(pp0[1], u1r0, u0r0);
                v1a = fma2(pp1[1], u1r1, u0r1);
            }
            {
                float4 c2 = cf[4 * j + 2], c3 = cf[4 * j + 3];
                float2 lo2 = make_float2(c2.x, c2.y), hi2 = make_float2(c2.z, c2.w);
                float2 lo3 = make_float2(c3.x, c3.y), hi3 = make_float2(c3.z, c3.w);
                float2 u2r0 = fma2(pp0[0], hi2, lo2);
                float2 u2r1 = fma2(pp1[0], hi2, lo2);
                float2 u3r0 = fma2(pp0[0], hi3, lo3);
                float2 u3r1 = fma2(pp1[0], hi3, lo3);
                v0b = fma2(pp0[1], u3r0, u2r0);
                v1b = fma2(pp1[1], u3r1, u2r1);
            }
            w0[j] = fma2(pp0[2], v0b, v0a);
            w1[j] = fma2(pp1[2], v1b, v1a);
        }
        float2 x0[4], x1[4];
        #pragma unroll
        for (int j = 0; j < 4; j++) {
            x0[j] = fma2(pp0[3], w0[2 * j + 1], w0[2 * j]);
            x1[j] = fma2(pp1[3], w1[2 * j + 1], w1[2 * j]);
        }
        float2 y00 = fma2(pp0[4], x0[1], x0[0]);
        float2 y01 = fma2(pp0[4], x0[3], x0[2]);
        float2 y10 = fma2(pp1[4], x1[1], x1[0]);
        float2 y11 = fma2(pp1[4], x1[3], x1[2]);
        res[k][0] = fma2(pp0[5], y01, y00);
        res[k][1] = fma2(pp1[5], y11, y10);
    }

    // store: 4 consecutive trees' (t0,t1) per row -> STG.128
    const int b0 = tileB + 2 * lane;
    float* o0 = out + (size_t)b0 * OUTW + grp * 64 + sub * 4;
    float* o1 = o0 + OUTW;
    *(float4*)o0 = make_float4(res[0][0].x, res[0][0].y, res[1][0].x, res[1][0].y);
    *(float4*)o1 = make_float4(res[0][1].x, res[0][1].y, res[1][1].x, res[1][1].y);
}

// ---------------------------------------------------------------------------
extern "C" void kernel_launch(void* const* d_in, const int* in_sizes, int n_in,
                              void* d_out, int out_size) {
    const float* inputs = (const float*)d_in[0];
    const float* fsl    = (const float*)d_in[1];
    const float* thr    = (const float*)d_in[2];
    const float* logT   = (const float*)d_in[3];
    const float* resp   = (const float*)d_in[4];
    float* out = (float*)d_out;

    cudaFuncSetAttribute(odt_main, cudaFuncAttributeMaxDynamicSharedMemorySize,
                         ODT_SMEM);

    prep_kernel<<<256, 256>>>(fsl, resp);

    cudaLaunchConfig_t cfg = {};
    cfg.gridDim = dim3(8, 32);
    cfg.blockDim = dim3(512);
    cfg.dynamicSmemBytes = ODT_SMEM;
    cudaLaunchAttribute attrs[1];
    attrs[0].id = cudaLaunchAttributeProgrammaticStreamSerialization;
    attrs[0].val.programmaticStreamSerializationAllowed = 1;
    cfg.attrs = attrs;
    cfg.numAttrs = 1;
    cudaLaunchKernelEx(&cfg, odt_main, inputs, thr, logT, out);
}

// round 17
// speedup vs baseline: 1.2322x; 1.0169x over previous
#include <cuda_runtime.h>

#define NUM_TREES 256
#define DEPTH 6
#define INPUT_DIM 256
#define BATCH 2048
#define NCOLS (NUM_TREES * DEPTH)   // 1536
#define MAXNZ 256
#define OUTW (NUM_TREES * 2)        // 512
#define TPAD 66                      // padded batch-tile row stride (floats)

// smem layout offsets (bytes)
#define OFF_PACK 67584                        // 256*66*4
#define OFF_COEF (OFF_PACK + 12288)           // 79872  (192 cols * 8 * 8B)
#define OFF_NNZ  (OFF_COEF + 16384)           // 96256
#define OFF_TH   (OFF_NNZ + 768)              // 97024
#define ODT_SMEM (OFF_TH + 1536)              // 98560

// Device scratch
__device__ float2 g_pack[NCOLS * MAXNZ];      // {prescaled idx*TPAD bits, weight}
__device__ int    g_nnz [NCOLS];              // >= 8, multiple of 4
__device__ float  g_coef[NUM_TREES * 64 * 2]; // multilinear coeffs [n][c][tdim]

// packed fp32x2 ops (Blackwell)
__device__ __forceinline__ float2 fma2(float2 a, float2 b, float2 c) {
    unsigned long long A, B, C, R;
    A = *reinterpret_cast<unsigned long long*>(&a);
    B = *reinterpret_cast<unsigned long long*>(&b);
    C = *reinterpret_cast<unsigned long long*>(&c);
    asm("fma.rn.f32x2 %0, %1, %2, %3;" : "=l"(R) : "l"(A), "l"(B), "l"(C));
    return *reinterpret_cast<float2*>(&R);
}
__device__ __forceinline__ float2 add2(float2 a, float2 b) {
    unsigned long long A, B, R;
    A = *reinterpret_cast<unsigned long long*>(&a);
    B = *reinterpret_cast<unsigned long long*>(&b);
    asm("add.rn.f32x2 %0, %1, %2;" : "=l"(R) : "l"(A), "l"(B));
    return *reinterpret_cast<float2*>(&R);
}

// ---------------------------------------------------------------------------
// Prep kernel: blocks 0..191  = sparsemax (8 columns each, Michelot) + compact
//              blocks 192..255 = response -> multilinear coefficient transform
// Michelot count via ballot+popc (no shuffle chain for the count).
// ---------------------------------------------------------------------------
__global__ void __launch_bounds__(256) prep_kernel(
    const float* __restrict__ fsl, const float* __restrict__ resp)
{
    cudaTriggerProgrammaticLaunchCompletion();

    const int tid  = threadIdx.x;
    const int warp = tid >> 5;
    const int lane = tid & 31;

    if (blockIdx.x < 192) {
        // ---- sparsemax over 8 columns ----
        __shared__ float s[INPUT_DIM * 9];   // [row][col] pad 9
        const int colBase = blockIdx.x * 8;
        #pragma unroll
        for (int k = 0; k < 8; k++) {
            int linear = k * 256 + tid;
            int r = linear >> 3, c = linear & 7;
            s[r * 9 + c] = fsl[r * NCOLS + colBase + c];
        }
        __syncthreads();

        const int col = colBase + warp;
        float v[8];
        #pragma unroll
        for (int j = 0; j < 8; j++) v[j] = s[(j * 32 + lane) * 9 + warp];

        float ss = v[0];
        #pragma unroll
        for (int j = 1; j < 8; j++) ss += v[j];
        #pragma unroll
        for (int o = 16; o > 0; o >>= 1) ss += __shfl_xor_sync(~0u, ss, o);
        float tau = (ss - 1.0f) / 256.0f;

        int cprev = 256;
        for (int it = 0; it < 64; it++) {
            float ps = 0.0f;
            int pc = 0;
            #pragma unroll
            for (int j = 0; j < 8; j++) {
                bool g = v[j] > tau;
                unsigned m = __ballot_sync(~0u, g);
                pc += __popc(m);                 // warp-uniform count, no shuffles
                if (g) ps += v[j];
            }
            #pragma unroll
            for (int o = 16; o > 0; o >>= 1)
                ps += __shfl_xor_sync(~0u, ps, o);
            tau = (ps - 1.0f) / (float)pc;
            if (pc == cprev) break;
            cprev = pc;
        }

        // compaction with prescaled offsets (idx * TPAD)
        const unsigned ltmask = (1u << lane) - 1u;
        int total = 0;
        #pragma unroll
        for (int j = 0; j < 8; j++) {
            float w = v[j] - tau;
            bool nz = (w > 0.0f);
            unsigned m = __ballot_sync(~0u, nz);
            if (nz) {
                int pos = total + __popc(m & ltmask);
                g_pack[col * MAXNZ + pos] =
                    make_float2(__int_as_float((j * 32 + lane) * TPAD), w);
            }
            total += __popc(m);
        }
        // pad to 8 minimum, else to multiple of 4
        int tot = (total <= 8) ? 8 : ((total + 3) & ~3);
        if (lane < tot - total)
            g_pack[col * MAXNZ + total + lane] = make_float2(__int_as_float(0), 0.0f);
        if (lane == 0) g_nnz[col] = tot;
    } else {
        // ---- coefficient transform: warp = (tree, tdim) ----
        const int cb = blockIdx.x - 192;
        const int n  = cb * 4 + (warp >> 1);
        const int t  = warp & 1;
        float r0 = resp[(n * 2 + t) * 64 + lane];
        float r1 = resp[(n * 2 + t) * 64 + 32 + lane];
        #pragma unroll
        for (int d = 0; d < 5; d++) {
            int m = 1 << d;
            float o0 = __shfl_xor_sync(~0u, r0, m);
            float o1 = __shfl_xor_sync(~0u, r1, m);
            bool hi = (lane >> d) & 1;
            r0 = hi ? (o0 - r0) : o0;
            r1 = hi ? (o1 - r1) : o1;
        }
        { float tmp = r0; r0 = r1; r1 = tmp - r1; }
        g_coef[(n * 64 + lane)      * 2 + t] = r0;
        g_coef[(n * 64 + 32 + lane) * 2 + t] = r1;
    }
}

// ---------------------------------------------------------------------------
// Main kernel (byte-identical to the banked R14 optimum): 512 threads,
// 32 trees x 64 rows; branch-free 8-entry gathers; PDL overlap with prep.
// ---------------------------------------------------------------------------
__global__ void __launch_bounds__(512, 2) odt_main(
    const float* __restrict__ inputs,
    const float* __restrict__ thr,
    const float* __restrict__ logT,
    float* __restrict__ out)
{
    extern __shared__ __align__(16) char smem[];
    float*  s_in    = (float*) smem;                 // [256][66]
    float4* s_pack4 = (float4*)(smem + OFF_PACK);    // [192][4] f4 (=8 f2)
    float4* s_coef4 = (float4*)(smem + OFF_COEF);    // [32][32] f4
    int*    s_nnz   = (int*)   (smem + OFF_NNZ);     // [192]
    float2* s_th    = (float2*)(smem + OFF_TH);      // [192] {bias, scale}

    const int tid  = threadIdx.x;
    const int lane = tid & 31;
    const int sub  = tid >> 5;
    const int grp  = blockIdx.x;          // 0..7
    const int tileB = blockIdx.y * 64;
    const int nBase = grp * 32;
    const int colBase = nBase * DEPTH;    // grp*192

    // ---- prep-independent staging ----
    #pragma unroll
    for (int e = 0; e < 32; e++) {
        int linear = e * 512 + tid;
        int i = linear & 255, b = linear >> 8;
        s_in[i * TPAD + b] = inputs[(tileB + b) * INPUT_DIM + i];
    }
    // folded threshold transform: t = acc*scale + bias
    if (tid < 192) {
        int gcol = colBase + tid;
        float sc = 0.5f * expf(-logT[gcol]);
        s_th[tid] = make_float2(0.5f - thr[gcol] * sc, sc);
    }

    // ---- wait for prep results, then stage them ----
    cudaGridDependencySynchronize();

    const float4* gp4 = (const float4*)g_pack;
    {
        int idx = tid;
        int cl = idx >> 2, j = idx & 3;
        s_pack4[idx] = gp4[(colBase + cl) * (MAXNZ / 2) + j];
        idx = 512 + tid;
        if (idx < 768) {
            cl = idx >> 2; j = idx & 3;
            s_pack4[idx] = gp4[(colBase + cl) * (MAXNZ / 2) + j];
        }
    }
    const float4* gc4 = (const float4*)g_coef;
    s_coef4[tid]       = gc4[nBase * 32 + tid];
    s_coef4[512 + tid] = gc4[nBase * 32 + 512 + tid];
    if (tid < 192) s_nnz[tid] = g_nnz[colBase + tid];
    __syncthreads();

    // warp-uniform overflow bitmask for this warp's 12 columns
    unsigned over = 0;
    #pragma unroll
    for (int q = 0; q < 12; q++)
        if (s_nnz[sub * 12 + q] > 8) over |= 1u << q;

    const int base2 = 2 * lane;
    float2 res[2][2];   // [k][row]

    #pragma unroll
    for (int k = 0; k < 2; k++) {
        const int nL = sub * 2 + k;

        // ---- branch-free gather fast path: acc for all 6 depths ----
        float2 acc[DEPTH];
        #pragma unroll
        for (int d = 0; d < DEPTH; d++) {
            const int colL = nL * DEPTH + d;
            const float4* pk = s_pack4 + colL * 4;
            float4 a = pk[0], b = pk[1], c = pk[2], e = pk[3];

            float2 x0 = *(const float2*)(s_in + __float_as_int(a.x) + base2);
            float2 x1 = *(const float2*)(s_in + __float_as_int(a.z) + base2);
            float2 x2 = *(const float2*)(s_in + __float_as_int(b.x) + base2);
            float2 x3 = *(const float2*)(s_in + __float_as_int(b.z) + base2);
            float2 x4 = *(const float2*)(s_in + __float_as_int(c.x) + base2);
            float2 x5 = *(const float2*)(s_in + __float_as_int(c.z) + base2);
            float2 x6 = *(const float2*)(s_in + __float_as_int(e.x) + base2);
            float2 x7 = *(const float2*)(s_in + __float_as_int(e.z) + base2);

            float2 a0 = make_float2(0.0f, 0.0f);
            float2 a1 = make_float2(0.0f, 0.0f);
            a0 = fma2(x0, make_float2(a.y, a.y), a0);
            a1 = fma2(x1, make_float2(a.w, a.w), a1);
            a0 = fma2(x2, make_float2(b.y, b.y), a0);
            a1 = fma2(x3, make_float2(b.w, b.w), a1);
            a0 = fma2(x4, make_float2(c.y, c.y), a0);
            a1 = fma2(x5, make_float2(c.w, c.w), a1);
            a0 = fma2(x6, make_float2(e.y, e.y), a0);
            a1 = fma2(x7, make_float2(e.w, e.w), a1);
            acc[d] = add2(a0, a1);
        }

        // ---- single rare patch branch for overflow columns ----
        if (over & (0x3fu << (k * 6))) {
            #pragma unroll
            for (int d = 0; d < DEPTH; d++) {
                if (over & (1u << (k * 6 + d))) {
                    const int colL = nL * DEPTH + d;
                    const int nn = s_nnz[colL];
                    const float2* gq = g_pack + (size_t)(colBase + colL) * MAXNZ;
                    for (int j = 8; j < nn; j++) {
                        float2 q = __ldg(gq + j);
                        float2 x = *(const float2*)(s_in + __float_as_int(q.x) + base2);
                        acc[d] = fma2(x, make_float2(q.y, q.y), acc[d]);
                    }
                }
            }
        }

        // ---- clip to p (packed threshold fma, scalar clips) ----
        float2 pp0[DEPTH], pp1[DEPTH];
        #pragma unroll
        for (int d = 0; d < DEPTH; d++) {
            float2 th = s_th[nL * DEPTH + d];
            float2 t = fma2(acc[d], make_float2(th.y, th.y),
                            make_float2(th.x, th.x));
            float pA = fminf(fmaxf(t.x, 0.0f), 1.0f);
            float pB = fminf(fmaxf(t.y, 0.0f), 1.0f);
            pp0[d] = make_float2(pA, pA);
            pp1[d] = make_float2(pB, pB);
        }

        // ---- multilinear evaluation, tdims packed ----
        const float4* cf = s_coef4 + nL * 32;
        float2 w0[8], w1[8];
        #pragma unroll
        for (int j = 0; j < 8; j++) {
            float2 v0a, v0b, v1a, v1b;
            {
                float4 c0 = cf[4 * j + 0], c1 = cf[4 * j + 1];
                float2 lo0 = make_float2(c0.x, c0.y), hi0 = make_float2(c0.z, c0.w);
                float2 lo1 = make_float2(c1.x, c1.y), hi1 = make_float2(c1.z, c1.w);
                float2 u0r0 = fma2(pp0[0], hi0, lo0);
                float2 u0r1 = fma2(pp1[0], hi0, lo0);
                float2 u1r0 = fma2(pp0[0], hi1, lo1);
                float2 u1r1 = fma2(pp1[0], hi1, lo1);
                v0a = fma2(pp0[1], u1r0, u0r0);
                v1a = fma2(pp1[1], u1r1, u0r1);
            }
            {
                float4 c2 = cf[4 * j + 2], c3 = cf[4 * j + 3];
                float2 lo2 = make_float2(c2.x, c2.y), hi2 = make_float2(c2.z, c2.w);
                float2 lo3 = make_float2(c3.x, c3.y), hi3 = make_float2(c3.z, c3.w);
                float2 u2r0 = fma2(pp0[0], hi2, lo2);
                float2 u2r1 = fma2(pp1[0], hi2, lo2);
                float2 u3r0 = fma2(pp0[0], hi3, lo3);
                float2 u3r1 = fma2(pp1[0], hi3, lo3);
                v0b = fma2(pp0[1], u3r0, u2r0);
                v1b = fma2(pp1[1], u3r1, u2r1);
            }
            w0[j] = fma2(pp0[2], v0b, v0a);
            w1[j] = fma2(pp1[2], v1b, v1a);
        }
        float2 x0[4], x1[4];
        #pragma unroll
        for (int j = 0; j < 4; j++) {
            x0[j] = fma2(pp0[3], w0[2 * j + 1], w0[2 * j]);
            x1[j] = fma2(pp1[3], w1[2 * j + 1], w1[2 * j]);
        }
        float2 y00 = fma2(pp0[4], x0[1], x0[0]);
        float2 y01 = fma2(pp0[4], x0[3], x0[2]);
        float2 y10 = fma2(pp1[4], x1[1], x1[0]);
        float2 y11 = fma2(pp1[4], x1[3], x1[2]);
        res[k][0] = fma2(pp0[5], y01, y00);
        res[k][1] = fma2(pp1[5], y11, y10);
    }

    // store: 4 consecutive trees' (t0,t1) per row -> STG.128
    const int b0 = tileB + 2 * lane;
    float* o0 = out + (size_t)b0 * OUTW + grp * 64 + sub * 4;
    float* o1 = o0 + OUTW;
    *(float4*)o0 = make_float4(res[0][0].x, res[0][0].y, res[1][0].x, res[1][0].y);
    *(float4*)o1 = make_float4(res[0][1].x, res[0][1].y, res[1][1].x, res[1][1].y);
}

// ---------------------------------------------------------------------------
extern "C" void kernel_launch(void* const* d_in, const int* in_sizes, int n_in,
                              void* d_out, int out_size) {
    const float* inputs = (const float*)d_in[0];
    const float* fsl    = (const float*)d_in[1];
    const float* thr    = (const float*)d_in[2];
    const float* logT   = (const float*)d_in[3];
    const float* resp   = (const float*)d_in[4];
    float* out = (float*)d_out;

    cudaFuncSetAttribute(odt_main, cudaFuncAttributeMaxDynamicSharedMemorySize,
                         ODT_SMEM);

    prep_kernel<<<256, 256>>>(fsl, resp);

    cudaLaunchConfig_t cfg = {};
    cfg.gridDim = dim3(8, 32);
    cfg.blockDim = dim3(512);
    cfg.dynamicSmemBytes = ODT_SMEM;
    cudaLaunchAttribute attrs[1];
    attrs[0].id = cudaLaunchAttributeProgrammaticStreamSerialization;
    attrs[0].val.programmaticStreamSerializationAllowed = 1;
    cfg.attrs = attrs;
    cfg.numAttrs = 1;
    cudaLaunchKernelEx(&cfg, odt_main, inputs, thr, logT, out);
}